// round 2
// baseline (speedup 1.0000x reference)
#include <cuda_runtime.h>
#include <cstdint>

#define BB   8
#define SRC  512
#define TGT  128
#define ED   512   // enc dim
#define DD   512   // dec dim (== K of score space)

// Scratch (device globals: allocation-free per harness rules)
__device__ float g_mp[BB * SRC * DD];   // 8 MB: memory @ Wa_m
__device__ float g_dp[BB * TGT * DD];   // 2 MB: decoder_state @ Wa_d

__device__ __forceinline__ float fast_tanh(float x) {
    float y;
    asm("tanh.approx.f32 %0, %1;" : "=f"(y) : "f"(x));
    return y;
}

// ---------------------------------------------------------------------------
// Projection GEMM: C[M,512] = A[M,512] @ W[512,512]
// BM=128, BN=64, BK=8, 256 threads, 8x4 micro-tile.
// grid: x = 512/64 = 8 n-blocks; y = 40 (32 mp m-blocks + 8 dp m-blocks)
// ---------------------------------------------------------------------------
__global__ void __launch_bounds__(256) gemm_pre(
    const float* __restrict__ memory,
    const float* __restrict__ dec,
    const float* __restrict__ Wa)
{
    __shared__ float As[8][132];   // transposed A tile, padded
    __shared__ float Bs[8][64];

    const int tid = threadIdx.x;
    const int bn  = blockIdx.x;
    const int by  = blockIdx.y;

    const float *A, *W;
    float *C;
    int bm;
    if (by < 32) { A = memory; W = Wa + 512 * 512; C = g_mp; bm = by; }
    else         { A = dec;    W = Wa;             C = g_dp; bm = by - 32; }

    const float* Ab = A + (size_t)bm * 128 * 512;
    const float* Wb = W + bn * 64;
    float*       Cb = C + (size_t)bm * 128 * 512 + bn * 64;

    const int arow = tid >> 1;             // 0..127
    const int acol = (tid & 1) * 4;        // 0 or 4
    const int brow = tid >> 5;             // 0..7
    const int bcol = (tid & 31) * 2;       // 0..62
    const int tr   = (tid >> 4) * 8;       // 0..120
    const int tc   = (tid & 15) * 4;       // 0..60

    float acc[8][4];
    #pragma unroll
    for (int i = 0; i < 8; i++)
        #pragma unroll
        for (int j = 0; j < 4; j++) acc[i][j] = 0.f;

    for (int k0 = 0; k0 < 512; k0 += 8) {
        float4 av = *(const float4*)(Ab + (size_t)arow * 512 + k0 + acol);
        As[acol + 0][arow] = av.x;
        As[acol + 1][arow] = av.y;
        As[acol + 2][arow] = av.z;
        As[acol + 3][arow] = av.w;
        float2 bv = *(const float2*)(Wb + (size_t)(k0 + brow) * 512 + bcol);
        *(float2*)(&Bs[brow][bcol]) = bv;
        __syncthreads();

        #pragma unroll
        for (int k = 0; k < 8; k++) {
            float rm[8], rn[4];
            *(float4*)(rm)     = *(const float4*)(&As[k][tr]);
            *(float4*)(rm + 4) = *(const float4*)(&As[k][tr + 4]);
            *(float4*)(rn)     = *(const float4*)(&Bs[k][tc]);
            #pragma unroll
            for (int i = 0; i < 8; i++)
                #pragma unroll
                for (int j = 0; j < 4; j++)
                    acc[i][j] = fmaf(rm[i], rn[j], acc[i][j]);
        }
        __syncthreads();
    }

    #pragma unroll
    for (int i = 0; i < 8; i++)
        *(float4*)(Cb + (size_t)(tr + i) * 512 + tc) = *(float4*)(acc[i]);
}

// ---------------------------------------------------------------------------
// Fused score + masked softmax + context.
// Block: b = blockIdx.y, t-tile of 8 (t = t0 + warp_id). 256 threads / 8 warps.
// Each warp owns one t; lanes own 4 s-values per 128-s tile (16 e-accs total,
// covering all 512 s) -> softmax is a pure warp-shuffle reduction.
// ---------------------------------------------------------------------------
__global__ void __launch_bounds__(256) attn_kernel(
    const float* __restrict__ memory,
    const float* __restrict__ Va,
    const int* __restrict__ mask,    // bool materialized as int32 by harness
    float* __restrict__ out)
{
    __shared__ float s_dp[8 * 512];         // 16 KB
    __shared__ float s_va[512];             //  2 KB
    __shared__ float s_mp[128 * 36];        // 18 KB, reused as s_a (8*512 fits)
    float* s_a = s_mp;

    const int b    = blockIdx.y;
    const int t0   = blockIdx.x * 8;
    const int tid  = threadIdx.x;
    const int lane = tid & 31;
    const int w    = tid >> 5;

    // stage dp rows for this t-tile + Va
    {
        const float4* dpg = (const float4*)(g_dp + (size_t)(b * TGT + t0) * 512);
        for (int i = tid; i < 8 * 512 / 4; i += 256) ((float4*)s_dp)[i] = dpg[i];
        if (tid < 128) ((float4*)s_va)[tid] = ((const float4*)Va)[tid];
    }
    __syncthreads();

    float e[16];
    #pragma unroll
    for (int i = 0; i < 16; i++) e[i] = 0.f;
    const float* dprow = s_dp + w * 512;

    const int r0 = tid >> 3;            // loader: 0..31
    const int c4 = (tid & 7) << 2;      // loader: 0..28

    #pragma unroll
    for (int st = 0; st < 4; st++) {
        const float* mpg = g_mp + (size_t)(b * SRC + st * 128) * 512;
        for (int kc = 0; kc < 512; kc += 32) {
            __syncthreads();
            #pragma unroll
            for (int rr = 0; rr < 128; rr += 32) {
                float4 v = *(const float4*)(mpg + (size_t)(r0 + rr) * 512 + kc + c4);
                *(float4*)(s_mp + (r0 + rr) * 36 + c4) = v;
            }
            __syncthreads();

            float* ep = e + st * 4;
            #pragma unroll
            for (int k = 0; k < 32; k += 4) {
                float4 d4 = *(const float4*)(dprow + kc + k);
                float4 v4 = *(const float4*)(s_va + kc + k);
                #pragma unroll
                for (int j = 0; j < 4; j++) {
                    float4 m4 = *(const float4*)(s_mp + (lane + 32 * j) * 36 + k);
                    float a0 = fast_tanh(d4.x + m4.x);
                    float a1 = fast_tanh(d4.y + m4.y);
                    float a2 = fast_tanh(d4.z + m4.z);
                    float a3 = fast_tanh(d4.w + m4.w);
                    ep[j] = fmaf(v4.x, a0, ep[j]);
                    ep[j] = fmaf(v4.y, a1, ep[j]);
                    ep[j] = fmaf(v4.z, a2, ep[j]);
                    ep[j] = fmaf(v4.w, a3, ep[j]);
                }
            }
        }
    }

    // mask + softmax (per-warp over all 512 s of t = w)
    const int* mrow = mask + b * SRC;
    const float NEG_INF = __int_as_float(0xff800000);
    float mx = NEG_INF;
    #pragma unroll
    for (int i = 0; i < 16; i++) {
        int s = (i >> 2) * 128 + (i & 3) * 32 + lane;
        if (mrow[s] == 0) e[i] = NEG_INF;
        mx = fmaxf(mx, e[i]);
    }
    #pragma unroll
    for (int o = 16; o; o >>= 1) mx = fmaxf(mx, __shfl_xor_sync(0xffffffffu, mx, o));
    float sum = 0.f;
    #pragma unroll
    for (int i = 0; i < 16; i++) {
        float p = __expf(e[i] - mx);
        e[i] = p;
        sum += p;
    }
    #pragma unroll
    for (int o = 16; o; o >>= 1) sum += __shfl_xor_sync(0xffffffffu, sum, o);
    float inv = 1.f / sum;

    __syncthreads();   // all warps done with s_mp before aliasing as s_a
    #pragma unroll
    for (int i = 0; i < 16; i++) {
        int s = (i >> 2) * 128 + (i & 3) * 32 + lane;
        s_a[w * 512 + s] = e[i] * inv;
    }
    __syncthreads();

    // context: out[b, t0+tg..+3, :] = a @ memory[b]   (memory[b] is L2-hot)
    const int cid = tid & 127;          // 128 col-groups of float4 -> 512 cols
    const int tg  = (tid >> 7) * 4;     // 0 or 4
    const float* memb = memory + (size_t)b * SRC * ED;

    float4 c[4];
    #pragma unroll
    for (int i = 0; i < 4; i++) c[i] = make_float4(0.f, 0.f, 0.f, 0.f);

    #pragma unroll 4
    for (int s = 0; s < SRC; s++) {
        float4 mv = *(const float4*)(memb + (size_t)s * ED + cid * 4);
        #pragma unroll
        for (int i = 0; i < 4; i++) {
            float av = s_a[(tg + i) * 512 + s];
            c[i].x = fmaf(av, mv.x, c[i].x);
            c[i].y = fmaf(av, mv.y, c[i].y);
            c[i].z = fmaf(av, mv.z, c[i].z);
            c[i].w = fmaf(av, mv.w, c[i].w);
        }
    }

    #pragma unroll
    for (int i = 0; i < 4; i++)
        *(float4*)(out + (size_t)(b * TGT + t0 + tg + i) * ED + cid * 4) = c[i];
}

// ---------------------------------------------------------------------------
extern "C" void kernel_launch(void* const* d_in, const int* in_sizes, int n_in,
                              void* d_out, int out_size)
{
    const float* memory = (const float*)d_in[0];
    const float* dec    = (const float*)d_in[1];
    const int*   mask   = (const int*)d_in[2];
    const float* Wa     = (const float*)d_in[3];
    const float* Va     = (const float*)d_in[4];
    float*       out    = (float*)d_out;

    (void)in_sizes; (void)n_in; (void)out_size;

    gemm_pre<<<dim3(8, 40), 256>>>(memory, dec, Wa);
    attn_kernel<<<dim3(TGT / 8, BB), 256>>>(memory, Va, mask, out);
}

// round 3
// speedup vs baseline: 1.0817x; 1.0817x over previous
#include <cuda_runtime.h>
#include <cstdint>

#define BB   8
#define SRC  512
#define TGT  128
#define ED   512
#define DD   512

// Scratch (device globals: allocation-free per harness rules)
__device__ float g_mp[BB * SRC * DD];   // 8 MB: memory @ Wa_m
__device__ float g_dp[BB * TGT * DD];   // 2 MB: decoder_state @ Wa_d
__device__ float g_a [BB * TGT * SRC];  // 2 MB: softmax probabilities

__device__ __forceinline__ float fast_tanh(float x) {
    float y;
    asm("tanh.approx.f32 %0, %1;" : "=f"(y) : "f"(x));
    return y;
}

// ---------------------------------------------------------------------------
// Projection GEMM: C[M,512] = A[M,512] @ W[512,512]
// BM=128, BN=64, BK=8, 256 threads, 8x4 micro-tile.
// grid: x = 8 n-blocks; y = 40 (32 mp m-blocks + 8 dp m-blocks)
// ---------------------------------------------------------------------------
__global__ void __launch_bounds__(256) gemm_pre(
    const float* __restrict__ memory,
    const float* __restrict__ dec,
    const float* __restrict__ Wa)
{
    __shared__ float As[8][132];
    __shared__ float Bs[8][64];

    const int tid = threadIdx.x;
    const int bn  = blockIdx.x;
    const int by  = blockIdx.y;

    const float *A, *W;
    float *C;
    int bm;
    if (by < 32) { A = memory; W = Wa + 512 * 512; C = g_mp; bm = by; }
    else         { A = dec;    W = Wa;             C = g_dp; bm = by - 32; }

    const float* Ab = A + (size_t)bm * 128 * 512;
    const float* Wb = W + bn * 64;
    float*       Cb = C + (size_t)bm * 128 * 512 + bn * 64;

    const int arow = tid >> 1;
    const int acol = (tid & 1) * 4;
    const int brow = tid >> 5;
    const int bcol = (tid & 31) * 2;
    const int tr   = (tid >> 4) * 8;
    const int tc   = (tid & 15) * 4;

    float acc[8][4];
    #pragma unroll
    for (int i = 0; i < 8; i++)
        #pragma unroll
        for (int j = 0; j < 4; j++) acc[i][j] = 0.f;

    for (int k0 = 0; k0 < 512; k0 += 8) {
        float4 av = *(const float4*)(Ab + (size_t)arow * 512 + k0 + acol);
        As[acol + 0][arow] = av.x;
        As[acol + 1][arow] = av.y;
        As[acol + 2][arow] = av.z;
        As[acol + 3][arow] = av.w;
        float2 bv = *(const float2*)(Wb + (size_t)(k0 + brow) * 512 + bcol);
        *(float2*)(&Bs[brow][bcol]) = bv;
        __syncthreads();

        #pragma unroll
        for (int k = 0; k < 8; k++) {
            float rm[8], rn[4];
            *(float4*)(rm)     = *(const float4*)(&As[k][tr]);
            *(float4*)(rm + 4) = *(const float4*)(&As[k][tr + 4]);
            *(float4*)(rn)     = *(const float4*)(&Bs[k][tc]);
            #pragma unroll
            for (int i = 0; i < 8; i++)
                #pragma unroll
                for (int j = 0; j < 4; j++)
                    acc[i][j] = fmaf(rm[i], rn[j], acc[i][j]);
        }
        __syncthreads();
    }

    #pragma unroll
    for (int i = 0; i < 8; i++)
        *(float4*)(Cb + (size_t)(tr + i) * 512 + tc) = *(float4*)(acc[i]);
}

// ---------------------------------------------------------------------------
// Score + masked softmax -> g_a.
// Block: b = blockIdx.y, 2 t-values (t = t0 + (w&1)); s-quarter q = w>>1.
// Each warp owns (t, 4 s-values/lane): s_j = 128*j + 32*q + lane, j=0..3.
// mp tile: 256 s-rows x 32 k, pitch 36 (conflict-free), 2 stages cover 512 s.
// Stage holds s in [256*stage, 256*stage+256) -> accumulators j = 2*stage+jj.
// Grid = 64 x 8 = 512 blocks; 43KB smem, <=64 regs -> 4 blocks/SM, 50% occ.
// ---------------------------------------------------------------------------
__global__ void __launch_bounds__(256, 4) score_kernel(
    const float* __restrict__ Va,
    const int* __restrict__ mask)
{
    __shared__ float s_mp[256 * 36];   // 36 KB
    __shared__ float s_dp[2 * 512];    //  4 KB
    __shared__ float s_va[512];        //  2 KB
    __shared__ float s_red[16];

    const int b    = blockIdx.y;
    const int t0   = blockIdx.x * 2;
    const int tid  = threadIdx.x;
    const int lane = tid & 31;
    const int w    = tid >> 5;
    const int tl   = w & 1;            // t_local
    const int q    = w >> 1;           // s-quarter 0..3

    // stage dp rows (t0, t0+1) and Va
    {
        const float4* dpg = (const float4*)(g_dp + (size_t)(b * TGT + t0) * 512);
        ((float4*)s_dp)[tid] = dpg[tid];                         // 256 float4
        if (tid < 128) ((float4*)s_va)[tid] = ((const float4*)Va)[tid];
    }

    float e[4] = {0.f, 0.f, 0.f, 0.f};
    const float* dprow = s_dp + tl * 512;

    const int r0 = tid >> 3;           // loader row 0..31
    const int c4 = (tid & 7) << 2;     // loader col 0..28
    const int myrow = 32 * q + lane;   // this lane's base tile row

    #pragma unroll
    for (int stage = 0; stage < 2; stage++) {
        const float* mpg = g_mp + (size_t)(b * SRC + stage * 256) * 512;
        float* ep = e + stage * 2;
        for (int kc = 0; kc < 512; kc += 32) {
            __syncthreads();
            #pragma unroll
            for (int rr = 0; rr < 256; rr += 32) {
                float4 v = *(const float4*)(mpg + (size_t)(r0 + rr) * 512 + kc + c4);
                *(float4*)(s_mp + (r0 + rr) * 36 + c4) = v;
            }
            __syncthreads();

            #pragma unroll
            for (int k = 0; k < 32; k += 4) {
                float4 d4 = *(const float4*)(dprow + kc + k);
                float4 v4 = *(const float4*)(s_va + kc + k);
                #pragma unroll
                for (int jj = 0; jj < 2; jj++) {
                    float4 m4 = *(const float4*)(s_mp + (128 * jj + myrow) * 36 + k);
                    float a0 = fast_tanh(d4.x + m4.x);
                    float a1 = fast_tanh(d4.y + m4.y);
                    float a2 = fast_tanh(d4.z + m4.z);
                    float a3 = fast_tanh(d4.w + m4.w);
                    ep[jj] = fmaf(v4.x, a0, ep[jj]);
                    ep[jj] = fmaf(v4.y, a1, ep[jj]);
                    ep[jj] = fmaf(v4.z, a2, ep[jj]);
                    ep[jj] = fmaf(v4.w, a3, ep[jj]);
                }
            }
        }
    }

    // mask
    const int* mrow = mask + b * SRC;
    const float NEG_INF = __int_as_float(0xff800000);
    #pragma unroll
    for (int j = 0; j < 4; j++) {
        int s = 128 * j + myrow;
        if (mrow[s] == 0) e[j] = NEG_INF;
    }

    // two-level max (warp -> 4 warps sharing t)
    float mx = fmaxf(fmaxf(e[0], e[1]), fmaxf(e[2], e[3]));
    #pragma unroll
    for (int o = 16; o; o >>= 1) mx = fmaxf(mx, __shfl_xor_sync(0xffffffffu, mx, o));
    if (lane == 0) s_red[tl * 4 + q] = mx;
    __syncthreads();
    float M = fmaxf(fmaxf(s_red[tl * 4 + 0], s_red[tl * 4 + 1]),
                    fmaxf(s_red[tl * 4 + 2], s_red[tl * 4 + 3]));

    // two-level sum
    float p[4], sum = 0.f;
    #pragma unroll
    for (int j = 0; j < 4; j++) { p[j] = __expf(e[j] - M); sum += p[j]; }
    #pragma unroll
    for (int o = 16; o; o >>= 1) sum += __shfl_xor_sync(0xffffffffu, sum, o);
    __syncthreads();                    // s_red max-phase consumed by all
    if (lane == 0) s_red[8 + tl * 4 + q] = sum;
    __syncthreads();
    float S = s_red[8 + tl * 4 + 0] + s_red[8 + tl * 4 + 1] +
              s_red[8 + tl * 4 + 2] + s_red[8 + tl * 4 + 3];
    float inv = 1.f / S;

    float* arow = g_a + (size_t)(b * TGT + t0 + tl) * SRC;
    #pragma unroll
    for (int j = 0; j < 4; j++) arow[128 * j + myrow] = p[j] * inv;
}

// ---------------------------------------------------------------------------
// Context GEMM: out[b] (128t x 512e) = g_a[b] (128 x 512s) @ memory[b] (512 x 512)
// BM=64 t, BN=32 cols, BK=32 s. Grid = (16 colblocks, 2 t-blocks, 8 b) = 256.
// 256 threads; thread: col = tid&31, rows (tid>>5)*8 .. +8.
// ---------------------------------------------------------------------------
__global__ void __launch_bounds__(256) context_kernel(
    const float* __restrict__ memory,
    float* __restrict__ out)
{
    __shared__ float As[64 * 32];      // a tile   (pitch 32; reads are broadcast)
    __shared__ float Bs[32 * 32];      // mem tile (lane==col -> conflict-free)

    const int cb  = blockIdx.x;        // col block
    const int tb  = blockIdx.y;        // t block
    const int b   = blockIdx.z;
    const int tid = threadIdx.x;
    const int col = tid & 31;
    const int tr0 = (tid >> 5) * 8;

    const float* Ab = g_a + (size_t)(b * TGT + tb * 64) * SRC;
    const float* Bb = memory + (size_t)b * SRC * ED + cb * 32;

    const int ar = tid >> 2;           // 0..63
    const int ac = (tid & 3) * 8;      // 0,8,16,24  (2 float4 per thread)
    const int br = tid >> 3;           // 0..31
    const int bc = (tid & 7) * 4;      // 0..28

    float acc[8];
    #pragma unroll
    for (int i = 0; i < 8; i++) acc[i] = 0.f;

    for (int sc = 0; sc < SRC; sc += 32) {
        __syncthreads();
        *(float4*)(As + ar * 32 + ac)     = *(const float4*)(Ab + (size_t)ar * SRC + sc + ac);
        *(float4*)(As + ar * 32 + ac + 4) = *(const float4*)(Ab + (size_t)ar * SRC + sc + ac + 4);
        *(float4*)(Bs + br * 32 + bc)     = *(const float4*)(Bb + (size_t)(sc + br) * ED + bc);
        __syncthreads();

        #pragma unroll
        for (int s = 0; s < 32; s++) {
            float bv = Bs[s * 32 + col];
            #pragma unroll
            for (int i = 0; i < 8; i++)
                acc[i] = fmaf(As[(tr0 + i) * 32 + s], bv, acc[i]);
        }
    }

    #pragma unroll
    for (int i = 0; i < 8; i++)
        out[(size_t)(b * TGT + tb * 64 + tr0 + i) * ED + cb * 32 + col] = acc[i];
}

// ---------------------------------------------------------------------------
extern "C" void kernel_launch(void* const* d_in, const int* in_sizes, int n_in,
                              void* d_out, int out_size)
{
    const float* memory = (const float*)d_in[0];
    const float* dec    = (const float*)d_in[1];
    const int*   mask   = (const int*)d_in[2];
    const float* Wa     = (const float*)d_in[3];
    const float* Va     = (const float*)d_in[4];
    float*       out    = (float*)d_out;

    (void)in_sizes; (void)n_in; (void)out_size;

    gemm_pre<<<dim3(8, 40), 256>>>(memory, dec, Wa);
    score_kernel<<<dim3(TGT / 2, BB), 256>>>(Va, mask);
    context_kernel<<<dim3(16, 2, BB), 256>>>(memory, out);
}

// round 4
// speedup vs baseline: 1.1764x; 1.0875x over previous
#include <cuda_runtime.h>
#include <cstdint>

#define BB   8
#define SRC  512
#define TGT  128
#define ED   512
#define DD   512
#define TT   4     // t-values per score block

// Scratch (device globals: allocation-free per harness rules)
__device__ float g_mp[BB * SRC * DD];   // 8 MB: memory @ Wa_m
__device__ float g_dp[BB * TGT * DD];   // 2 MB: decoder_state @ Wa_d
__device__ float g_a [BB * TGT * SRC];  // 2 MB: softmax probabilities

__device__ __forceinline__ float fast_tanh(float x) {
    float y;
    asm("tanh.approx.f32 %0, %1;" : "=f"(y) : "f"(x));
    return y;
}

// ---------------------------------------------------------------------------
// Projection GEMM: C[M,512] = A[M,512] @ W[512,512]
// BM=128, BN=64, BK=16, 256 threads, 8x4 micro-tile.
// Double-buffered smem, one barrier per k-iter, LDG prefetch into registers.
// grid: x = 8 n-blocks; y = 40 (32 mp m-blocks + 8 dp m-blocks)
// ---------------------------------------------------------------------------
__global__ void __launch_bounds__(256) gemm_pre(
    const float* __restrict__ memory,
    const float* __restrict__ dec,
    const float* __restrict__ Wa)
{
    __shared__ float As[2][16][132];   // transposed A tile, padded
    __shared__ float Bs[2][16][64];

    const int tid = threadIdx.x;
    const int bn  = blockIdx.x;
    const int by  = blockIdx.y;

    const float *A, *W;
    float *C;
    int bm;
    if (by < 32) { A = memory; W = Wa + 512 * 512; C = g_mp; bm = by; }
    else         { A = dec;    W = Wa;             C = g_dp; bm = by - 32; }

    const float* Ab = A + (size_t)bm * 128 * 512;
    const float* Wb = W + bn * 64;
    float*       Cb = C + (size_t)bm * 128 * 512 + bn * 64;

    const int arow = tid >> 1;             // 0..127
    const int acol = (tid & 1) * 8;        // 0 or 8 (two float4)
    const int brow = tid >> 4;             // 0..15
    const int bcol = (tid & 15) * 4;       // 0..60
    const int tr   = (tid >> 4) * 8;       // 0..120
    const int tc   = (tid & 15) * 4;       // 0..60

    float acc[8][4];
    #pragma unroll
    for (int i = 0; i < 8; i++)
        #pragma unroll
        for (int j = 0; j < 4; j++) acc[i][j] = 0.f;

    // prefetch k0 = 0
    float4 a0 = *(const float4*)(Ab + (size_t)arow * 512 + acol);
    float4 a1 = *(const float4*)(Ab + (size_t)arow * 512 + acol + 4);
    float4 b0 = *(const float4*)(Wb + (size_t)brow * 512 + bcol);

    int p = 0;
    for (int it = 0; it < 32; it++) {
        As[p][acol + 0][arow] = a0.x;
        As[p][acol + 1][arow] = a0.y;
        As[p][acol + 2][arow] = a0.z;
        As[p][acol + 3][arow] = a0.w;
        As[p][acol + 4][arow] = a1.x;
        As[p][acol + 5][arow] = a1.y;
        As[p][acol + 6][arow] = a1.z;
        As[p][acol + 7][arow] = a1.w;
        *(float4*)(&Bs[p][brow][bcol]) = b0;
        __syncthreads();

        if (it < 31) {
            const int k0 = (it + 1) * 16;
            a0 = *(const float4*)(Ab + (size_t)arow * 512 + k0 + acol);
            a1 = *(const float4*)(Ab + (size_t)arow * 512 + k0 + acol + 4);
            b0 = *(const float4*)(Wb + (size_t)(k0 + brow) * 512 + bcol);
        }

        #pragma unroll
        for (int k = 0; k < 16; k++) {
            float rm[8], rn[4];
            *(float4*)(rm)     = *(const float4*)(&As[p][k][tr]);
            *(float4*)(rm + 4) = *(const float4*)(&As[p][k][tr + 4]);
            *(float4*)(rn)     = *(const float4*)(&Bs[p][k][tc]);
            #pragma unroll
            for (int i = 0; i < 8; i++)
                #pragma unroll
                for (int j = 0; j < 4; j++)
                    acc[i][j] = fmaf(rm[i], rn[j], acc[i][j]);
        }
        p ^= 1;
    }

    #pragma unroll
    for (int i = 0; i < 8; i++)
        *(float4*)(Cb + (size_t)(tr + i) * 512 + tc) = *(float4*)(acc[i]);
}

// ---------------------------------------------------------------------------
// Score + masked softmax -> g_a.   (MUFU-bound stage: 268M tanh)
// Block: b = blockIdx.y, TT=4 t-values. 8 warps; in each s-stage (256 rows)
// warp w / lane l owns ONE s-row: s = stage*256 + w*32 + lane, accumulating
// full k for all 4 t. Per k-step (4 k): 1 m4 load + 4 dp broadcasts + 1 va
// load feed 16 tanh -> LDS traffic ~28% of MUFU capacity (was ~100% in v1).
// acc[stage*TT + t] = e[t, s(stage)]. Tile pitch 36 -> conflict-free LDS.128.
// ---------------------------------------------------------------------------
__global__ void __launch_bounds__(256, 4) score_kernel(
    const float* __restrict__ Va,
    const int* __restrict__ mask)
{
    __shared__ float s_mp[256 * 36];    // 36 KB
    __shared__ float s_dp[TT * 512];    //  8 KB
    __shared__ float s_va[512];         //  2 KB
    __shared__ float s_red[TT * 8];

    const int b    = blockIdx.y;
    const int t0   = blockIdx.x * TT;
    const int tid  = threadIdx.x;
    const int lane = tid & 31;
    const int w    = tid >> 5;

    // stage dp rows (t0..t0+3) and Va
    {
        const float4* dpg = (const float4*)(g_dp + (size_t)(b * TGT + t0) * 512);
        ((float4*)s_dp)[tid]       = dpg[tid];
        ((float4*)s_dp)[tid + 256] = dpg[tid + 256];
        if (tid < 128) ((float4*)s_va)[tid] = ((const float4*)Va)[tid];
    }

    float acc[2 * TT];
    #pragma unroll
    for (int i = 0; i < 2 * TT; i++) acc[i] = 0.f;

    const int r0    = tid >> 3;          // loader row 0..31
    const int c4    = (tid & 7) << 2;    // loader col 0..28
    const int myrow = w * 32 + lane;     // this lane's tile row (0..255)

    #pragma unroll
    for (int stage = 0; stage < 2; stage++) {
        const float* mpg = g_mp + (size_t)(b * SRC + stage * 256) * 512;
        float* ep = acc + stage * TT;
        for (int kc = 0; kc < 512; kc += 32) {
            __syncthreads();
            #pragma unroll
            for (int rr = 0; rr < 256; rr += 32) {
                float4 v = *(const float4*)(mpg + (size_t)(r0 + rr) * 512 + kc + c4);
                *(float4*)(s_mp + (r0 + rr) * 36 + c4) = v;
            }
            __syncthreads();

            const float* mrow_s = s_mp + myrow * 36;
            #pragma unroll
            for (int k = 0; k < 32; k += 4) {
                float4 m4 = *(const float4*)(mrow_s + k);
                float4 v4 = *(const float4*)(s_va + kc + k);
                #pragma unroll
                for (int t = 0; t < TT; t++) {
                    float4 d4 = *(const float4*)(s_dp + t * 512 + kc + k);
                    float a0 = fast_tanh(d4.x + m4.x);
                    float a1 = fast_tanh(d4.y + m4.y);
                    float a2 = fast_tanh(d4.z + m4.z);
                    float a3 = fast_tanh(d4.w + m4.w);
                    ep[t] = fmaf(v4.x, a0, ep[t]);
                    ep[t] = fmaf(v4.y, a1, ep[t]);
                    ep[t] = fmaf(v4.z, a2, ep[t]);
                    ep[t] = fmaf(v4.w, a3, ep[t]);
                }
            }
        }
    }

    // mask (this lane's two s positions)
    const int* mk = mask + b * SRC;
    const int s0 = myrow, s1 = 256 + myrow;
    const float NEG_INF = __int_as_float(0xff800000);
    const bool m0 = (mk[s0] != 0), m1 = (mk[s1] != 0);
    #pragma unroll
    for (int t = 0; t < TT; t++) {
        if (!m0) acc[t]      = NEG_INF;
        if (!m1) acc[TT + t] = NEG_INF;
    }

    // block max per t
    float mx[TT];
    #pragma unroll
    for (int t = 0; t < TT; t++) {
        float m = fmaxf(acc[t], acc[TT + t]);
        #pragma unroll
        for (int o = 16; o; o >>= 1) m = fmaxf(m, __shfl_xor_sync(0xffffffffu, m, o));
        if (lane == 0) s_red[t * 8 + w] = m;
    }
    __syncthreads();
    #pragma unroll
    for (int t = 0; t < TT; t++) {
        float m = s_red[t * 8 + 0];
        #pragma unroll
        for (int i = 1; i < 8; i++) m = fmaxf(m, s_red[t * 8 + i]);
        mx[t] = m;
    }
    __syncthreads();

    // block sum per t
    float inv[TT];
    #pragma unroll
    for (int t = 0; t < TT; t++) {
        float p0 = __expf(acc[t]      - mx[t]);
        float p1 = __expf(acc[TT + t] - mx[t]);
        acc[t] = p0; acc[TT + t] = p1;
        float s = p0 + p1;
        #pragma unroll
        for (int o = 16; o; o >>= 1) s += __shfl_xor_sync(0xffffffffu, s, o);
        if (lane == 0) s_red[t * 8 + w] = s;
    }
    __syncthreads();
    #pragma unroll
    for (int t = 0; t < TT; t++) {
        float s = s_red[t * 8 + 0];
        #pragma unroll
        for (int i = 1; i < 8; i++) s += s_red[t * 8 + i];
        inv[t] = 1.f / s;
    }

    #pragma unroll
    for (int t = 0; t < TT; t++) {
        float* arow = g_a + (size_t)(b * TGT + t0 + t) * SRC;
        arow[s0] = acc[t]      * inv[t];
        arow[s1] = acc[TT + t] * inv[t];
    }
}

// ---------------------------------------------------------------------------
// Context GEMM: out[b] (128t x 512e) = g_a[b] (128 x 512s) @ memory[b] (512 x 512)
// BM=64 t, BN=32 cols, BK=32 s. Grid = (16, 2, 8) = 256 blocks, 256 threads.
// ---------------------------------------------------------------------------
__global__ void __launch_bounds__(256) context_kernel(
    const float* __restrict__ memory,
    float* __restrict__ out)
{
    __shared__ float As[64 * 32];
    __shared__ float Bs[32 * 32];

    const int cb  = blockIdx.x;
    const int tb  = blockIdx.y;
    const int b   = blockIdx.z;
    const int tid = threadIdx.x;
    const int col = tid & 31;
    const int tr0 = (tid >> 5) * 8;

    const float* Ab = g_a + (size_t)(b * TGT + tb * 64) * SRC;
    const float* Bb = memory + (size_t)b * SRC * ED + cb * 32;

    const int ar = tid >> 2;
    const int ac = (tid & 3) * 8;
    const int br = tid >> 3;
    const int bc = (tid & 7) * 4;

    float acc[8];
    #pragma unroll
    for (int i = 0; i < 8; i++) acc[i] = 0.f;

    for (int sc = 0; sc < SRC; sc += 32) {
        __syncthreads();
        *(float4*)(As + ar * 32 + ac)     = *(const float4*)(Ab + (size_t)ar * SRC + sc + ac);
        *(float4*)(As + ar * 32 + ac + 4) = *(const float4*)(Ab + (size_t)ar * SRC + sc + ac + 4);
        *(float4*)(Bs + br * 32 + bc)     = *(const float4*)(Bb + (size_t)(sc + br) * ED + bc);
        __syncthreads();

        #pragma unroll
        for (int s = 0; s < 32; s++) {
            float bv = Bs[s * 32 + col];
            #pragma unroll
            for (int i = 0; i < 8; i++)
                acc[i] = fmaf(As[(tr0 + i) * 32 + s], bv, acc[i]);
        }
    }

    #pragma unroll
    for (int i = 0; i < 8; i++)
        out[(size_t)(b * TGT + tb * 64 + tr0 + i) * ED + cb * 32 + col] = acc[i];
}

// ---------------------------------------------------------------------------
extern "C" void kernel_launch(void* const* d_in, const int* in_sizes, int n_in,
                              void* d_out, int out_size)
{
    const float* memory = (const float*)d_in[0];
    const float* dec    = (const float*)d_in[1];
    const int*   mask   = (const int*)d_in[2];
    const float* Wa     = (const float*)d_in[3];
    const float* Va     = (const float*)d_in[4];
    float*       out    = (float*)d_out;

    (void)in_sizes; (void)n_in; (void)out_size;

    gemm_pre<<<dim3(8, 40), 256>>>(memory, dec, Wa);
    score_kernel<<<dim3(TGT / TT, BB), 256>>>(Va, mask);
    context_kernel<<<dim3(16, 2, BB), 256>>>(memory, out);
}